// round 2
// baseline (speedup 1.0000x reference)
#include <cuda_runtime.h>
#include <cuda_bf16.h>

#define NN 50000
#define EE 800000
#define DD 128

// ---------------- scratch (device globals: no allocation allowed) ----------
__device__ float g_bufA[(size_t)NN * DD];   // h * dis   (per layer)
__device__ float g_bufB[(size_t)NN * DD];   // scatter accumulator (layer 1)
__device__ float g_dis[NN];
__device__ int   g_deg[NN];
__device__ int   g_src[EE];
__device__ int   g_dst[EE];
__device__ int   g_is64;

// ---------------- f32x2 helpers (sm_103a packed fp32) ----------------------
__device__ __forceinline__ unsigned long long pack2(float lo, float hi) {
    unsigned long long r;
    asm("mov.b64 %0, {%1, %2};" : "=l"(r) : "f"(lo), "f"(hi));
    return r;
}
__device__ __forceinline__ void unpack2(unsigned long long v, float& lo, float& hi) {
    asm("mov.b64 {%0, %1}, %2;" : "=f"(lo), "=f"(hi) : "l"(v));
}
__device__ __forceinline__ void fma2(unsigned long long& acc,
                                     unsigned long long a, unsigned long long b) {
    asm("fma.rn.f32x2 %0, %1, %2, %3;" : "=l"(acc) : "l"(a), "l"(b), "l"(acc));
}

// ---------------- dtype detect ---------------------------------------------
// edge_index is declared int64 in the reference, but JAX without x64 silently
// emits int32. For int64 little-endian values < 50000, every odd 32-bit word
// is 0; for random int32 indices that's (50000^-64)-improbable.
__global__ void detect_kernel(const int* __restrict__ ei32) {
    if (threadIdx.x == 0 && blockIdx.x == 0) {
        int is64 = 1;
        for (int i = 0; i < 64; i++)
            if (ei32[2 * i + 1] != 0) { is64 = 0; break; }
        g_is64 = is64;
    }
}

// ---------------- graph prep ----------------------------------------------
__global__ void init_deg_kernel(int n) {
    int i = blockIdx.x * blockDim.x + threadIdx.x;
    if (i < n) g_deg[i] = 1;  // self-loop
}

__global__ void prep_edges_kernel(const void* __restrict__ ei_raw, int E, int n) {
    int e = blockIdx.x * blockDim.x + threadIdx.x;
    if (e >= E) return;
    int s, d;
    if (g_is64) {
        const long long* ei = (const long long*)ei_raw;
        s = (int)ei[e];
        d = (int)ei[(size_t)E + e];
    } else {
        const int* ei = (const int*)ei_raw;
        s = ei[e];
        d = ei[(size_t)E + e];
    }
    // clamp defensively (bad index -> harmless, correctness run would catch)
    if (s < 0) s = 0; if (s >= n) s = n - 1;
    if (d < 0) d = 0; if (d >= n) d = n - 1;
    g_src[e] = s;
    g_dst[e] = d;
    atomicAdd(&g_deg[d], 1);
}

__global__ void calc_dis_kernel(int n) {
    int i = blockIdx.x * blockDim.x + threadIdx.x;
    if (i < n) g_dis[i] = rsqrtf((float)g_deg[i]);
}

// ---------------- fused GEMM ------------------------------------------------
// out[r][c] = dis[r] * sum_k pre(X[r][k]) * W[k][c]
// pre(x) = PRE ? relu(dis[r]*x + preb[k]) : x
// Block: 256 threads, 64 rows per block. X tile in smem (32KB), W via L1.
template <bool PRE>
__global__ void __launch_bounds__(256) gemm_kernel(
    const float* __restrict__ X, const float* __restrict__ W,
    const float* __restrict__ preb, float* __restrict__ out, int n)
{
    __shared__ float Xs[64 * DD];

    const int tid  = threadIdx.x;
    const int row0 = blockIdx.x * 64;

    // load X tile (with optional fused relu(dis*x + b) pre-op)
    const float4* X4  = (const float4*)X;
    float4*       Xs4 = (float4*)Xs;
    #pragma unroll
    for (int i = tid; i < 64 * 32; i += 256) {
        int r  = i >> 5;
        int c4 = i & 31;
        int gr = row0 + r;
        float4 v = make_float4(0.f, 0.f, 0.f, 0.f);
        if (gr < n) {
            v = X4[(size_t)gr * 32 + c4];
            if (PRE) {
                float dr = g_dis[gr];
                float4 bb = ((const float4*)preb)[c4];
                v.x = fmaxf(fmaf(dr, v.x, bb.x), 0.f);
                v.y = fmaxf(fmaf(dr, v.y, bb.y), 0.f);
                v.z = fmaxf(fmaf(dr, v.z, bb.z), 0.f);
                v.w = fmaxf(fmaf(dr, v.w, bb.w), 0.f);
            }
        }
        Xs4[i] = v;
    }
    __syncthreads();

    const int tx = tid & 31;   // column group: cols 4*tx .. 4*tx+3
    const int ty = tid >> 5;   // row group:    rows ty*8 .. ty*8+7

    unsigned long long acc[8][2];
    #pragma unroll
    for (int r = 0; r < 8; r++) { acc[r][0] = 0ull; acc[r][1] = 0ull; }

    const float4* W4 = (const float4*)W;
    #pragma unroll 8
    for (int k = 0; k < DD; k++) {
        float4 w = __ldg(&W4[k * 32 + tx]);
        unsigned long long w0 = pack2(w.x, w.y);
        unsigned long long w1 = pack2(w.z, w.w);
        #pragma unroll
        for (int r = 0; r < 8; r++) {
            float xv = Xs[(ty * 8 + r) * DD + k];   // warp-uniform broadcast
            unsigned long long xp = pack2(xv, xv);
            fma2(acc[r][0], xp, w0);
            fma2(acc[r][1], xp, w1);
        }
    }

    // epilogue: multiply by dis[row] (fold of symmetric normalization)
    #pragma unroll
    for (int r = 0; r < 8; r++) {
        int gr = row0 + ty * 8 + r;
        if (gr < n) {
            float ds = g_dis[gr];
            float a0, a1, a2, a3;
            unpack2(acc[r][0], a0, a1);
            unpack2(acc[r][1], a2, a3);
            float4 o = make_float4(a0 * ds, a1 * ds, a2 * ds, a3 * ds);
            ((float4*)out)[(size_t)gr * 32 + tx] = o;
        }
    }
}

// ---------------- scatter: acc[dst] += g[src], warp per message -------------
__global__ void scatter_kernel(const float* __restrict__ g,
                               float* __restrict__ acc, int E, int n)
{
    int warp = (blockIdx.x * blockDim.x + threadIdx.x) >> 5;
    int lane = threadIdx.x & 31;
    if (warp >= E + n) return;
    int s, d;
    if (warp < E) { s = g_src[warp]; d = g_dst[warp]; }
    else          { s = d = warp - E; }               // self-loop message

    float4 v = ((const float4*)(g + (size_t)s * DD))[lane];
    float* p = acc + (size_t)d * DD + lane * 4;
    asm volatile("red.global.add.v4.f32 [%0], {%1, %2, %3, %4};"
                 :: "l"(p), "f"(v.x), "f"(v.y), "f"(v.z), "f"(v.w)
                 : "memory");
}

// ---------------- finalize: out = relu(dis[r]*out + b2[c]) in place ---------
__global__ void finalize_kernel(float* __restrict__ out,
                                const float* __restrict__ b, int n)
{
    int i = blockIdx.x * blockDim.x + threadIdx.x;
    int total = n * DD;
    if (i >= total) return;
    int r = i >> 7;
    int c = i & 127;
    out[i] = fmaxf(fmaf(g_dis[r], out[i], b[c]), 0.f);
}

// ---------------- launch ----------------------------------------------------
extern "C" void kernel_launch(void* const* d_in, const int* in_sizes, int n_in,
                              void* d_out, int out_size)
{
    const float* x   = (const float*)d_in[0];
    const void*  ei  = d_in[1];
    const float* W1  = (const float*)d_in[2];
    const float* b1  = (const float*)d_in[3];
    const float* W2  = (const float*)d_in[4];
    const float* b2  = (const float*)d_in[5];
    float*       out = (float*)d_out;

    const int n = in_sizes[0] / DD;   // 50000
    const int E = in_sizes[1] / 2;    // 800000 (element count same for i32/i64)

    void *pA = nullptr, *pB = nullptr;
    cudaGetSymbolAddress(&pA, g_bufA);
    cudaGetSymbolAddress(&pB, g_bufB);
    float* bufA = (float*)pA;
    float* bufB = (float*)pB;

    const int T = 256;
    const int gemm_grid = (n + 63) / 64;
    const int msg_warps = E + n;
    const int scat_grid = (msg_warps * 32 + T - 1) / T;

    // graph prep
    detect_kernel<<<1, 32>>>((const int*)ei);
    init_deg_kernel<<<(n + T - 1) / T, T>>>(n);
    prep_edges_kernel<<<(E + T - 1) / T, T>>>(ei, E, n);
    calc_dis_kernel<<<(n + T - 1) / T, T>>>(n);

    // layer 1
    gemm_kernel<false><<<gemm_grid, T>>>(x, W1, nullptr, bufA, n);   // g1 = (x@W1)*dis
    cudaMemsetAsync(bufB, 0, (size_t)n * DD * sizeof(float));
    scatter_kernel<<<scat_grid, T>>>(bufA, bufB, E, n);              // acc1[dst]+=g1[src]

    // layer 2 (relu(dis*acc1+b1) fused into tile load)
    gemm_kernel<true><<<gemm_grid, T>>>(bufB, W2, b1, bufA, n);      // g2
    cudaMemsetAsync(out, 0, (size_t)n * DD * sizeof(float));
    scatter_kernel<<<scat_grid, T>>>(bufA, out, E, n);               // acc2[dst]+=g2[src]

    // out = relu(dis*acc2 + b2)
    finalize_kernel<<<((n * DD) + T - 1) / T, T>>>(out, b2, n);
}